// round 2
// baseline (speedup 1.0000x reference)
#include <cuda_runtime.h>
#include <cstdint>

#define BLOCK   256
#define IT      4         // i-rows per thread (register blocking)
#define JS      256       // smem j-tile
#define NSLICES 32        // j-range split for grid parallelism

// Per-block partials (no cudaMalloc allowed). .x = sum (w_i+w_j)*viol, .y = count
__device__ float2 g_partials[8192];

__global__ __launch_bounds__(BLOCK)
void rank_loss_partial(const float* __restrict__ pred,
                       const float* __restrict__ targ,
                       const float* __restrict__ wgt,
                       const int*   __restrict__ ms_raw,
                       int n, int numIChunks, int jsLen)
{
    __shared__ float sT[JS], sP[JS], sW[JS];
    __shared__ float redT[BLOCK / 32], redC[BLOCK / 32];

    const int tid    = threadIdx.x;
    const int ichunk = blockIdx.x / NSLICES;
    const int jslice = blockIdx.x % NSLICES;

    // margin_scale: python int -> int32 most likely; tolerate f32 too.
    int raw = *ms_raw;
    float ms = (raw > -100000 && raw < 100000) ? (float)raw : __int_as_float(raw);
    const float c = 0.08f * ms;   // margin = c * clip(|td|, 0.1, 1.0)

    const float FNAN = __int_as_float(0x7fffffff);

    // Load this thread's IT i-rows
    float ti[IT], pi[IT], wi[IT];
    const int i0 = ichunk * (BLOCK * IT) + tid;
#pragma unroll
    for (int k = 0; k < IT; k++) {
        int i = i0 + k * BLOCK;
        if (i < n) { ti[k] = targ[i]; pi[k] = pred[i]; wi[k] = wgt[i]; }
        else       { ti[k] = FNAN;    pi[k] = 0.0f;    wi[k] = 0.0f;  }
    }

    float accV[IT], accWV[IT];
    int   acnt[IT];
#pragma unroll
    for (int k = 0; k < IT; k++) { accV[k] = 0.0f; accWV[k] = 0.0f; acnt[k] = 0; }

    const int jBeg = jslice * jsLen;
    const int jEnd = min(jBeg + jsLen, n);

    for (int jt = jBeg; jt < jEnd; jt += JS) {
        // Fill smem tile (BLOCK == JS); NaN-pad invalid slots -> pair never valid
        {
            int j = jt + tid;
            bool ok = (j < jEnd);
            sT[tid] = ok ? targ[j] : FNAN;
            sP[tid] = ok ? pred[j] : 0.0f;
            sW[tid] = ok ? wgt[j]  : 0.0f;
        }
        __syncthreads();

        const int tlen = min(JS, jEnd - jt);
#pragma unroll 8
        for (int j = 0; j < tlen; j++) {
            const float tj = sT[j];
            const float pj = sP[j];
            const float wj = sW[j];
#pragma unroll
            for (int k = 0; k < IT; k++) {
                float td    = ti[k] - tj;                       // FADD (fma pipe)
                float ad    = fabsf(td);                        // folded as |td| modifier
                float mclip = fminf(fmaxf(ad, 0.1f), 1.0f);     // 2x FMNMX (fma pipe)
                float pd    = pi[k] - pj;                       // FADD (fma pipe)
                // x = -sign(td)*pd : flip pd's sign iff td > 0 (one LOP3, alu pipe)
                unsigned flip = (~__float_as_uint(td)) & 0x80000000u;
                float x     = __uint_as_float(__float_as_uint(pd) ^ flip);
                float viol  = fmaxf(fmaf(c, mclip, x), 0.0f);   // FFMA + FMNMX
                if (ad >= 0.05f) {            // FSETP (alu); NaN -> false masks padding
                    accV[k]  += viol;                           // @P FADD  (fma pipe)
                    accWV[k]  = fmaf(wj, viol, accWV[k]);       // @P FFMA  (fma pipe)
                    acnt[k]  += 1;                              // @P IADD3 (alu pipe)
                }
            }
        }
        __syncthreads();
    }

    // Combine: (w_i + w_j) * viol  ==  w_i * accV + accWV
    float tot = 0.0f, cnt = 0.0f;
#pragma unroll
    for (int k = 0; k < IT; k++) {
        tot += fmaf(wi[k], accV[k], accWV[k]);
        cnt += (float)acnt[k];
    }

    // Warp reduce
#pragma unroll
    for (int off = 16; off > 0; off >>= 1) {
        tot += __shfl_down_sync(0xffffffffu, tot, off);
        cnt += __shfl_down_sync(0xffffffffu, cnt, off);
    }
    if ((tid & 31) == 0) { redT[tid >> 5] = tot; redC[tid >> 5] = cnt; }
    __syncthreads();

    if (tid < 32) {
        float t2 = (tid < BLOCK / 32) ? redT[tid] : 0.0f;
        float c2 = (tid < BLOCK / 32) ? redC[tid] : 0.0f;
#pragma unroll
        for (int off = 4; off > 0; off >>= 1) {
            t2 += __shfl_down_sync(0xffffffffu, t2, off);
            c2 += __shfl_down_sync(0xffffffffu, c2, off);
        }
        if (tid == 0) g_partials[blockIdx.x] = make_float2(t2, c2);
    }
}

__global__ void rank_loss_finalize(float* __restrict__ out, int nPartials)
{
    __shared__ double sdT[8], sdC[8];
    const int tid = threadIdx.x;

    double t = 0.0, c = 0.0;
    for (int i = tid; i < nPartials; i += blockDim.x) {
        float2 p = g_partials[i];
        t += (double)p.x;
        c += (double)p.y;
    }
#pragma unroll
    for (int off = 16; off > 0; off >>= 1) {
        t += __shfl_down_sync(0xffffffffu, t, off);
        c += __shfl_down_sync(0xffffffffu, c, off);
    }
    if ((tid & 31) == 0) { sdT[tid >> 5] = t; sdC[tid >> 5] = c; }
    __syncthreads();
    if (tid < 32) {
        double t2 = (tid < 8) ? sdT[tid] : 0.0;
        double c2 = (tid < 8) ? sdC[tid] : 0.0;
#pragma unroll
        for (int off = 4; off > 0; off >>= 1) {
            t2 += __shfl_down_sync(0xffffffffu, t2, off);
            c2 += __shfl_down_sync(0xffffffffu, c2, off);
        }
        if (tid == 0)
            out[0] = (c2 > 0.0) ? (float)(0.5 * t2 / c2) : 0.0f;
    }
}

extern "C" void kernel_launch(void* const* d_in, const int* in_sizes, int n_in,
                              void* d_out, int out_size)
{
    const float* pred = (const float*)d_in[0];
    const float* targ = (const float*)d_in[1];
    const float* wgt  = (const float*)d_in[2];
    const int*   msp  = (const int*)  d_in[3];
    float* out = (float*)d_out;

    int n = in_sizes[0];
    int numIChunks = (n + BLOCK * IT - 1) / (BLOCK * IT);
    int jsLen      = (n + NSLICES - 1) / NSLICES;
    int grid       = numIChunks * NSLICES;   // n=8192 -> 256 blocks

    rank_loss_partial<<<grid, BLOCK>>>(pred, targ, wgt, msp, n, numIChunks, jsLen);
    rank_loss_finalize<<<1, 256>>>(out, grid);
}